// round 1
// baseline (speedup 1.0000x reference)
#include <cuda_runtime.h>

#define NN 10000
#define TT 50
#define Bn 2
#define Hn 64
#define BH 128          // Bn*Hn
#define IND 128         // input feature dim
#define EMAX 160000
#define CHUNK 16        // nodes per block in step kernel

// ---------------- device scratch (no allocation allowed) ----------------
__device__ float d_h[2][NN * BH];          // double-buffered hidden state [node][b*H+h]
__device__ int   d_deg_in[NN];
__device__ int   d_deg_out[NN];
__device__ float d_norm_s[NN];
__device__ float d_norm_d[NN];
__device__ int   d_row_ptr[NN + 1];
__device__ int   d_fill_ptr[NN];
__device__ int   d_csr_src[EMAX];
__device__ float d_csr_w[EMAX];
__device__ float d_xproj[3 * BH];          // [r|z|h][b][j]

// ---------------- precompute kernels ----------------
__global__ void init_kernel() {
    int i0 = blockIdx.x * blockDim.x + threadIdx.x;
    int stride = gridDim.x * blockDim.x;
    float4 z4 = make_float4(0.f, 0.f, 0.f, 0.f);
    float4* h0 = (float4*)d_h[0];
    for (int i = i0; i < NN * BH / 4; i += stride) h0[i] = z4;
    for (int i = i0; i < NN; i += stride) { d_deg_in[i] = 0; d_deg_out[i] = 0; }
}

__global__ void hist_kernel(const int* __restrict__ src, const int* __restrict__ dst, int E) {
    int e = blockIdx.x * blockDim.x + threadIdx.x;
    if (e < E) {
        atomicAdd(&d_deg_out[src[e]], 1);
        atomicAdd(&d_deg_in[dst[e]], 1);
    }
}

__global__ void norm_kernel() {
    int i = blockIdx.x * blockDim.x + threadIdx.x;
    if (i < NN) {
        d_norm_s[i] = rsqrtf((float)max(d_deg_out[i], 1));
        d_norm_d[i] = rsqrtf((float)max(d_deg_in[i], 1));
    }
}

// single-block inclusive-scan over deg_in -> row_ptr (exclusive into fill_ptr)
__global__ void scan_kernel() {
    __shared__ int sm[1024];
    int tid = threadIdx.x;
    int carry = 0;
    if (tid == 0) d_row_ptr[0] = 0;
    for (int base = 0; base < NN; base += 1024) {
        int i = base + tid;
        int v = (i < NN) ? d_deg_in[i] : 0;
        sm[tid] = v;
        __syncthreads();
        for (int off = 1; off < 1024; off <<= 1) {
            int tv = (tid >= off) ? sm[tid - off] : 0;
            __syncthreads();
            sm[tid] += tv;
            __syncthreads();
        }
        int incl = sm[tid];
        int tot  = sm[1023];
        if (i < NN) {
            d_row_ptr[i + 1] = carry + incl;
            d_fill_ptr[i]    = carry + incl - v;
        }
        carry += tot;
        __syncthreads();
    }
}

__global__ void scatter_kernel(const int* __restrict__ src, const int* __restrict__ dst, int E) {
    int e = blockIdx.x * blockDim.x + threadIdx.x;
    if (e < E) {
        int s = src[e], d = dst[e];
        int pos = atomicAdd(&d_fill_ptr[d], 1);
        d_csr_src[pos] = s;
        d_csr_w[pos]   = d_norm_d[d] * d_norm_s[s];
    }
}

// time-invariant input projections: xproj[p][b][j] = x[b] @ W_p + b_p
__global__ void xproj_kernel(const float* __restrict__ x,
                             const float* __restrict__ wr, const float* __restrict__ br,
                             const float* __restrict__ wz, const float* __restrict__ bz,
                             const float* __restrict__ wh, const float* __restrict__ bh) {
    __shared__ float xs[Bn * IND];
    int tid = threadIdx.x;
    if (tid < Bn * IND) xs[tid] = x[tid];
    __syncthreads();
    if (tid < 3 * BH) {
        int p = tid / BH, r = tid % BH, b = r / Hn, j = r % Hn;
        const float* W    = (p == 0) ? wr : (p == 1) ? wz : wh;
        const float* bias = (p == 0) ? br : (p == 1) ? bz : bh;
        float s = bias[j];
        #pragma unroll 8
        for (int k = 0; k < IND; k++)
            s += xs[b * IND + k] * W[k * Hn + j];
        d_xproj[tid] = s;
    }
}

// ---------------- fused GCN-GRU timestep ----------------
// phase 1: warp-per-node CSR gather-reduce into smem (agg = A_norm @ h)
// phase 2: channel-per-thread matvec (W column in registers), gates, state update, output
__global__ __launch_bounds__(256, 2) void step_kernel(
    const float* __restrict__ gcn_w, const float* __restrict__ gcn_b,
    float* __restrict__ out, int t) {
    __shared__ __align__(16) float agg_s[CHUNK * BH];
    __shared__ float xg_s[3 * BH];

    const float* __restrict__ h_prev = d_h[t & 1];
    float* __restrict__ h_next = d_h[(t & 1) ^ 1];

    for (int i = threadIdx.x; i < 3 * BH; i += 256) xg_s[i] = d_xproj[i];

    int warp = threadIdx.x >> 5, lane = threadIdx.x & 31;
    int node0 = blockIdx.x * CHUNK;

    // ---- phase 1: aggregation ----
    #pragma unroll
    for (int r = 0; r < CHUNK / 8; r++) {
        int ln = warp + r * 8;
        int node = node0 + ln;
        float4 acc = make_float4(0.f, 0.f, 0.f, 0.f);
        int beg = d_row_ptr[node], end = d_row_ptr[node + 1];
        for (int p = beg; p < end; p++) {
            int s = d_csr_src[p];
            float w = d_csr_w[p];
            float4 v = *(const float4*)&h_prev[s * BH + lane * 4];
            acc.x += w * v.x; acc.y += w * v.y;
            acc.z += w * v.z; acc.w += w * v.w;
        }
        *(float4*)&agg_s[ln * BH + lane * 4] = acc;
    }
    __syncthreads();

    // ---- phase 2: g = agg @ W + b, gates, update ----
    int j  = threadIdx.x & 63;   // output channel
    int pg = threadIdx.x >> 6;   // pair group 0..3
    float Wreg[64];
    #pragma unroll
    for (int k = 0; k < 64; k++) Wreg[k] = gcn_w[k * 64 + j];
    float bias_j = gcn_b[j];

    for (int pi = pg; pi < CHUNK * 2; pi += 4) {
        int ln = pi >> 1, b = pi & 1;
        int node = node0 + ln;
        const float* a = &agg_s[ln * BH + b * Hn];
        float g = bias_j;
        #pragma unroll
        for (int k = 0; k < 64; k += 4) {
            float4 av = *(const float4*)&a[k];
            g = fmaf(av.x, Wreg[k],     g);
            g = fmaf(av.y, Wreg[k + 1], g);
            g = fmaf(av.z, Wreg[k + 2], g);
            g = fmaf(av.w, Wreg[k + 3], g);
        }
        int bj = b * Hn + j;
        float r = __fdividef(1.f, 1.f + __expf(-(xg_s[bj] + g)));
        float z = __fdividef(1.f, 1.f + __expf(-(xg_s[BH + bj] + g)));
        float targ = xg_s[2 * BH + bj] + r * g;
        // tanh(x) = 2*sigmoid(2x) - 1  (NaN-safe at extremes)
        float ht = __fdividef(2.f, 1.f + __expf(-2.f * targ)) - 1.f;
        float hold = h_prev[node * BH + bj];
        float hn = (1.f - z) * hold + z * ht;
        h_next[node * BH + bj] = hn;
        out[((size_t)(b * TT + t) * NN + node) * Hn + j] = hn;
    }
}

// ---------------- launch ----------------
extern "C" void kernel_launch(void* const* d_in, const int* in_sizes, int n_in,
                              void* d_out, int out_size) {
    const float* x    = (const float*)d_in[0];
    const int*   src  = (const int*)  d_in[1];
    const int*   dst  = (const int*)  d_in[2];
    const float* wr   = (const float*)d_in[3];
    const float* br   = (const float*)d_in[4];
    const float* wz   = (const float*)d_in[5];
    const float* bz   = (const float*)d_in[6];
    const float* wh   = (const float*)d_in[7];
    const float* bh   = (const float*)d_in[8];
    const float* gw   = (const float*)d_in[9];
    const float* gb   = (const float*)d_in[10];
    float* out = (float*)d_out;
    int E = in_sizes[1];

    init_kernel<<<256, 256>>>();
    hist_kernel<<<(E + 255) / 256, 256>>>(src, dst, E);
    norm_kernel<<<(NN + 255) / 256, 256>>>();
    scan_kernel<<<1, 1024>>>();
    scatter_kernel<<<(E + 255) / 256, 256>>>(src, dst, E);
    xproj_kernel<<<1, 512>>>(x, wr, br, wz, bz, wh, bh);

    for (int t = 0; t < TT; t++) {
        step_kernel<<<NN / CHUNK, 256>>>(gw, gb, out, t);
    }
}